// round 9
// baseline (speedup 1.0000x reference)
#include <cuda_runtime.h>
#include <math.h>
#include <stdint.h>

// VimMamba: bidirectional Mamba block, fp32 SIMT.
// [b][l][d] layouts, gather conv, dir-batched mid GEMMs, pipelined scan,
// combine/silu fused into out_proj's A-loader.
// B=4, L=512, D_MODEL=1024, D_INNER=2048, D_STATE=16, DT_RANK=64, D_CONV=4

#define BB   4
#define LL   512
#define DM   1024
#define DS   16
#define DI   2048
#define RNK  64
#define XPC  96   // DT_RANK + 2*D_STATE

// ---------------- scratch (static device globals; no allocation) ----------------
__device__ __align__(16) float g_x[(size_t)BB * LL * DI];           // x part,  [b][l][d]
__device__ __align__(16) float g_z[(size_t)BB * LL * DI];           // z part,  [b][l][d]
__device__ __align__(16) float g_xc[(size_t)2 * BB * LL * DI];      // conv out (unclipped), [dir][b][t][d]
__device__ __align__(16) float g_xdbl[(size_t)2 * BB * LL * XPC];   // x_proj out, [dir][b][t][96]
__device__ __align__(16) float g_delta[(size_t)2 * BB * LL * DI];   // softplus dt, [dir][b][t][d]
__device__ __align__(16) float g_ys[(size_t)2 * BB * LL * DI];      // scan out, [dir][b][t][d]

enum { EPI_INPROJ = 0, EPI_PLAIN = 1, EPI_DT = 2, EPI_OUT = 3 };

__device__ __forceinline__ float silu_f(float z) {
    return z / (1.f + __expf(-z));
}

// ---------------- generic fp32 GEMM: C = A(MxK,row-major,lda) * W(NxK,row-major,ldb)^T ----
// Two-stage smem double buffer + register prefetch: one __syncthreads per K-step.
// EPI_OUT: A is synthesized on the fly as (ys_f + rev(ys_b)) * silu(z);
//          A = ys fwd base, W2 = z base, bias2 = ys bwd base (reused slots).
// Other EPIs may batch directions via blockIdx.z (W2/bias2 = dir-1 weights).
template <int BM, int BN, int BK, int TM, int TN, int EPI>
__global__ __launch_bounds__((BM / TM) * (BN / TN))
void gemm_k(const float* __restrict__ A, int lda,
            const float* __restrict__ W, int ldb,
            float* __restrict__ C, int ldc,
            const float* __restrict__ bias,
            float* __restrict__ C2,
            int K,
            const float* __restrict__ W2 = nullptr,
            const float* __restrict__ bias2 = nullptr,
            size_t aStride = 0, size_t cStride = 0)
{
    constexpr int NT   = (BM / TM) * (BN / TN);
    constexpr int NTX  = BN / TN;
    constexpr int KV   = BK / 4;                       // float4s per k-row
    constexpr int A_IT = (BM * KV + NT - 1) / NT;      // float4 loads/thread (A)
    constexpr int B_IT = (BN * KV + NT - 1) / NT;      // float4 loads/thread (B)

    if constexpr (EPI != EPI_OUT) {
        if (blockIdx.z) {                              // dir-batched launch
            A += aStride;
            C += cStride;
            W = W2;
            bias = bias2;
        }
    }

    const float* __restrict__ zBase  = W2;     // EPI_OUT only
    const float* __restrict__ ybBase = bias2;  // EPI_OUT only

    __shared__ float As[2][BK][BM + 4];
    __shared__ float Bs[2][BK][BN + 4];

    const int tid = threadIdx.x;
    const int tx  = tid % NTX;
    const int ty  = tid / NTX;
    const int m0  = blockIdx.y * BM;
    const int n0  = blockIdx.x * BN;

    float4 aReg[A_IT], bReg[B_IT];

    auto ldgA = [&](int k0) {
#pragma unroll
        for (int q = 0; q < A_IT; q++) {
            const int i = tid + q * NT;
            if (A_IT * NT == BM * KV || i < BM * KV) {
                const int r = i / KV, c = i % KV;
                if constexpr (EPI == EPI_OUT) {
                    // synthesize (ys_f + rev(ys_b)) * silu(z) for row m0+r, cols k0+4c..+3
                    const int row = m0 + r;
                    const int b   = row / LL, l = row % LL;
                    const size_t off  = (size_t)row * lda + k0 + c * 4;
                    const size_t offb = ((size_t)b * LL + (LL - 1 - l)) * lda + k0 + c * 4;
                    const float4 yf = *reinterpret_cast<const float4*>(A + off);
                    const float4 yb = *reinterpret_cast<const float4*>(ybBase + offb);
                    const float4 zv = *reinterpret_cast<const float4*>(zBase + off);
                    float4 v;
                    v.x = (yf.x + yb.x) * silu_f(zv.x);
                    v.y = (yf.y + yb.y) * silu_f(zv.y);
                    v.z = (yf.z + yb.z) * silu_f(zv.z);
                    v.w = (yf.w + yb.w) * silu_f(zv.w);
                    aReg[q] = v;
                } else {
                    aReg[q] = *reinterpret_cast<const float4*>(
                        A + (size_t)(m0 + r) * lda + k0 + c * 4);
                }
            }
        }
    };
    auto ldgB = [&](int k0) {
#pragma unroll
        for (int q = 0; q < B_IT; q++) {
            const int i = tid + q * NT;
            if (B_IT * NT == BN * KV || i < BN * KV) {
                const int r = i / KV, c = i % KV;
                bReg[q] = *reinterpret_cast<const float4*>(
                    W + (size_t)(n0 + r) * ldb + k0 + c * 4);
            }
        }
    };
    auto stsAB = [&](int s) {
#pragma unroll
        for (int q = 0; q < A_IT; q++) {
            const int i = tid + q * NT;
            if (A_IT * NT == BM * KV || i < BM * KV) {
                const int r = i / KV, c = i % KV;
                As[s][c * 4 + 0][r] = aReg[q].x;
                As[s][c * 4 + 1][r] = aReg[q].y;
                As[s][c * 4 + 2][r] = aReg[q].z;
                As[s][c * 4 + 3][r] = aReg[q].w;
            }
        }
#pragma unroll
        for (int q = 0; q < B_IT; q++) {
            const int i = tid + q * NT;
            if (B_IT * NT == BN * KV || i < BN * KV) {
                const int r = i / KV, c = i % KV;
                Bs[s][c * 4 + 0][r] = bReg[q].x;
                Bs[s][c * 4 + 1][r] = bReg[q].y;
                Bs[s][c * 4 + 2][r] = bReg[q].z;
                Bs[s][c * 4 + 3][r] = bReg[q].w;
            }
        }
    };

    float acc[TM][TN];
#pragma unroll
    for (int i = 0; i < TM; i++)
#pragma unroll
        for (int j = 0; j < TN; j++) acc[i][j] = 0.f;

    ldgA(0);
    ldgB(0);
    stsAB(0);
    __syncthreads();

    int s = 0;
    for (int k0 = 0; k0 < K; k0 += BK) {
        const bool more = (k0 + BK < K);
        if (more) {            // prefetch next tile into registers
            ldgA(k0 + BK);
            ldgB(k0 + BK);
        }

#pragma unroll
        for (int kk = 0; kk < BK; kk++) {
            float a[TM], b[TN];
#pragma unroll
            for (int q = 0; q < TM / 4; q++)
                *reinterpret_cast<float4*>(&a[q * 4]) =
                    *reinterpret_cast<const float4*>(&As[s][kk][ty * TM + q * 4]);
            if constexpr (TN % 4 == 0) {
#pragma unroll
                for (int q = 0; q < TN / 4; q++)
                    *reinterpret_cast<float4*>(&b[q * 4]) =
                        *reinterpret_cast<const float4*>(&Bs[s][kk][tx * TN + q * 4]);
            } else {
                *reinterpret_cast<float2*>(b) =
                    *reinterpret_cast<const float2*>(&Bs[s][kk][tx * TN]);
            }
#pragma unroll
            for (int i = 0; i < TM; i++)
#pragma unroll
                for (int j = 0; j < TN; j++) acc[i][j] += a[i] * b[j];
        }

        if (more) {            // publish next stage; single barrier per step
            stsAB(s ^ 1);
            __syncthreads();
        }
        s ^= 1;
    }

    // epilogue
#pragma unroll
    for (int i = 0; i < TM; i++) {
        const int r = m0 + ty * TM + i;
#pragma unroll
        for (int j = 0; j < TN; j++) {
            const int c = n0 + tx * TN + j;
            float v = acc[i][j];
            if constexpr (EPI == EPI_INPROJ) {
                // x and z both in [b][l][d] layout -> fully coalesced stores
                if (c < DI)
                    C[(size_t)r * DI + c] = v;
                else
                    C2[(size_t)r * DI + (c - DI)] = v;
            } else if constexpr (EPI == EPI_PLAIN) {
                C[(size_t)r * ldc + c] = v;
            } else if constexpr (EPI == EPI_DT) {
                float t = v + bias[c];
                t = fminf(fmaxf(t, 1e-5f), 1.0f) + bias[c];
                C[(size_t)r * ldc + c] = (t > 20.f) ? t : log1pf(expf(t));
            } else {  // EPI_OUT: nan_to_num(nan=0, posinf=1, neginf=-1)
                if (isnan(v)) v = 0.f;
                else if (isinf(v)) v = (v > 0.f) ? 1.f : -1.f;
                C[(size_t)r * ldc + c] = v;
            }
        }
    }
}

// ---------------- depthwise causal conv, gather-based (parallel over all outputs) ----------
__global__ void conv_k(const float* __restrict__ wf, const float* __restrict__ bf,
                       const float* __restrict__ wb, const float* __restrict__ bb)
{
    const int idx = blockIdx.x * blockDim.x + threadIdx.x;
    if (idx >= 2 * BB * LL * DI) return;
    const int d   = idx % DI;
    const int t   = (idx / DI) % LL;
    const int b   = (idx / (DI * LL)) % BB;
    const int dir = idx / (DI * LL * BB);

    const float4 w = *reinterpret_cast<const float4*>((dir ? wb : wf) + d * 4);
    float acc = (dir ? bb : bf)[d];

    const float* xb = g_x + (size_t)b * LL * DI;
#pragma unroll
    for (int j = 0; j < 4; j++) {
        const int tt = t - 3 + j;                 // position in (possibly reversed) seq
        if (tt >= 0) {
            const int src_l = dir ? (LL - 1 - tt) : tt;
            const float wj = j == 0 ? w.x : j == 1 ? w.y : j == 2 ? w.z : w.w;
            acc += wj * xb[(size_t)src_l * DI + d];
        }
    }
    g_xc[(size_t)idx] = acc;
}

// ---------------- selective scan (one thread per (dir,b,d), 16 states in regs) --------------
// Register-pipelined: t+1 inputs load while t computes.
__global__ void scan_k(const float* __restrict__ Alog_f, const float* __restrict__ Df,
                       const float* __restrict__ Alog_b, const float* __restrict__ Db)
{
    const int gid = blockIdx.x * blockDim.x + threadIdx.x;
    if (gid >= 2 * BB * DI) return;
    const int dir = gid / (BB * DI);
    const int rem = gid % (BB * DI);
    const int b = rem / DI, d = rem % DI;

    const float* Alog = dir ? Alog_b : Alog_f;
    const float  Dv   = dir ? Db[d] : Df[d];

    float Av[DS];
    bool fast = true;
#pragma unroll
    for (int n = 0; n < DS; n++) {
        Av[n] = -expf(Alog[d * DS + n]);
        fast = fast && (fabsf(Av[n] + (float)(n + 1)) < 1e-3f);
    }

    float h[DS];
#pragma unroll
    for (int n = 0; n < DS; n++) h[n] = 0.f;

    const size_t rowbase = (size_t)(dir * BB + b) * LL;
    const float* up = g_xc    + rowbase * DI  + d;
    const float* dp = g_delta + rowbase * DI  + d;
    const float* bc = g_xdbl  + rowbase * XPC + RNK;   // B then C, 32 floats
    float*       yp = g_ys    + rowbase * DI  + d;

    // prefetch t=0
    float  u_c   = up[0];
    float  dlt_c = dp[0];
    float4 q_c[8];
#pragma unroll
    for (int k = 0; k < 8; k++)
        q_c[k] = reinterpret_cast<const float4*>(bc)[k];

    for (int t = 0; t < LL; t++) {
        // issue t+1 loads first (independent of current compute)
        float  u_n = 0.f, dlt_n = 0.f;
        float4 q_n[8];
        if (t + 1 < LL) {
            u_n   = up[(size_t)(t + 1) * DI];
            dlt_n = dp[(size_t)(t + 1) * DI];
            const float4* qq = reinterpret_cast<const float4*>(bc + (size_t)(t + 1) * XPC);
#pragma unroll
            for (int k = 0; k < 8; k++) q_n[k] = qq[k];
        }

        const float u   = fminf(fmaxf(u_c, -10.f), 10.f);
        const float dlt = dlt_c;

        float Bv[DS], Cv[DS];
#pragma unroll
        for (int k = 0; k < 4; k++) *reinterpret_cast<float4*>(&Bv[k * 4]) = q_c[k];
#pragma unroll
        for (int k = 0; k < 4; k++) *reinterpret_cast<float4*>(&Cv[k * 4]) = q_c[4 + k];

        const float du = dlt * u;
        float y = u * Dv;
        if (fast) {
            // A[n] == -(n+1): need E^(n+1), E = exp(-dlt). Log-depth power tree.
            const float E1  = __expf(-dlt);
            const float E2  = E1 * E1;
            const float E3  = E2 * E1;
            const float E4  = E2 * E2;
            const float E8  = E4 * E4;
            const float E12 = E8 * E4;
            float pw[DS];
            pw[0]  = E1;        pw[1]  = E2;        pw[2]  = E3;        pw[3]  = E4;
            pw[4]  = E4 * E1;   pw[5]  = E4 * E2;   pw[6]  = E4 * E3;   pw[7]  = E8;
            pw[8]  = E8 * E1;   pw[9]  = E8 * E2;   pw[10] = E8 * E3;   pw[11] = E12;
            pw[12] = E12 * E1;  pw[13] = E12 * E2;  pw[14] = E12 * E3;  pw[15] = E8 * E8;
#pragma unroll
            for (int n = 0; n < DS; n++) {
                h[n] = pw[n] * h[n] + du * Bv[n];
                y += h[n] * Cv[n];
            }
        } else {
#pragma unroll
            for (int n = 0; n < DS; n++) {
                const float dA = __expf(dlt * Av[n]);
                h[n] = dA * h[n] + du * Bv[n];
                y += h[n] * Cv[n];
            }
        }
        yp[(size_t)t * DI] = y;

        // rotate buffers
        u_c = u_n; dlt_c = dlt_n;
#pragma unroll
        for (int k = 0; k < 8; k++) q_c[k] = q_n[k];
    }
}

// ---------------- host ----------------
extern "C" void kernel_launch(void* const* d_in, const int* in_sizes, int n_in,
                              void* d_out, int out_size)
{
    (void)in_sizes; (void)n_in; (void)out_size;

    const float* hidden  = (const float*)d_in[0];
    const float* inw     = (const float*)d_in[1];
    const float* convw_f = (const float*)d_in[2];
    const float* convb_f = (const float*)d_in[3];
    const float* xpw_f   = (const float*)d_in[4];
    const float* dtw_f   = (const float*)d_in[5];
    const float* dtb_f   = (const float*)d_in[6];
    const float* Alog_f  = (const float*)d_in[7];
    const float* Dv_f    = (const float*)d_in[8];
    const float* convw_b = (const float*)d_in[9];
    const float* convb_b = (const float*)d_in[10];
    const float* xpw_b   = (const float*)d_in[11];
    const float* dtw_b   = (const float*)d_in[12];
    const float* dtb_b   = (const float*)d_in[13];
    const float* Alog_b  = (const float*)d_in[14];
    const float* Dv_b    = (const float*)d_in[15];
    const float* outw    = (const float*)d_in[16];

    float *p_x, *p_z, *p_xc, *p_xdbl, *p_delta, *p_ys;
    cudaGetSymbolAddress((void**)&p_x,     g_x);
    cudaGetSymbolAddress((void**)&p_z,     g_z);
    cudaGetSymbolAddress((void**)&p_xc,    g_xc);
    cudaGetSymbolAddress((void**)&p_xdbl,  g_xdbl);
    cudaGetSymbolAddress((void**)&p_delta, g_delta);
    cudaGetSymbolAddress((void**)&p_ys,    g_ys);

    const int MROWS = BB * LL;  // 2048

    // 1) in_proj: (2048x1024) @ (4096x1024)^T -> split into x and z (both [b][l][d])
    gemm_k<128, 128, 16, 8, 8, EPI_INPROJ>
        <<<dim3((2 * DI) / 128, MROWS / 128), 256>>>(hidden, DM, inw, DM,
                                                     p_x, 0, nullptr, p_z, DM);

    // 2) depthwise causal conv, both directions (gather form, coalesced)
    conv_k<<<(2 * BB * LL * DI) / 256, 256>>>(convw_f, convb_f, convw_b, convb_b);

    // 3) x_proj, both directions in ONE launch (blockIdx.z = dir): 192 CTAs
    gemm_k<64, 32, 16, 4, 2, EPI_PLAIN>
        <<<dim3(XPC / 32, MROWS / 64, 2), 256>>>(
            p_xc, DI, xpw_f, DI, p_xdbl, XPC, nullptr, nullptr, DI,
            xpw_b, nullptr, (size_t)MROWS * DI, (size_t)MROWS * XPC);

    // 4) dt_proj (+clip+softplus), both directions in ONE launch: 512 CTAs
    gemm_k<128, 128, 16, 8, 8, EPI_DT>
        <<<dim3(DI / 128, MROWS / 128, 2), 256>>>(
            p_xdbl, XPC, dtw_f, RNK, p_delta, DI, dtb_f, nullptr, RNK,
            dtw_b, dtb_b, (size_t)MROWS * XPC, (size_t)MROWS * DI);

    // 5) selective scan, both directions (register-pipelined)
    scan_k<<<(2 * BB * DI) / 128, 128>>>(Alog_f, Dv_f, Alog_b, Dv_b);

    // 6) out_proj with fused combine+silu in the A-loader -> d_out (with nan_to_num)
    //    A = ys fwd base; W2 slot = z base; bias2 slot = ys bwd base.
    gemm_k<128, 128, 16, 8, 8, EPI_OUT>
        <<<dim3(DM / 128, MROWS / 128), 256>>>(
            p_ys, DI, outw, DI, (float*)d_out, DM, nullptr, nullptr, DI,
            p_z, p_ys + (size_t)BB * LL * DI, 0, 0);
}

// round 12
// speedup vs baseline: 1.0715x; 1.0715x over previous
#include <cuda_runtime.h>
#include <math.h>
#include <stdint.h>

// VimMamba: bidirectional Mamba block, fp32 SIMT.
// [b][l][d] layouts, vectorized gather conv, dir-batched mid GEMMs, pipelined scan,
// combine/silu fused into out_proj's A-loader, float4 epilogue stores,
// out_proj retiled 128x64 for full-chip occupancy.
// B=4, L=512, D_MODEL=1024, D_INNER=2048, D_STATE=16, DT_RANK=64, D_CONV=4

#define BB   4
#define LL   512
#define DM   1024
#define DS   16
#define DI   2048
#define RNK  64
#define XPC  96   // DT_RANK + 2*D_STATE

// ---------------- scratch (static device globals; no allocation) ----------------
__device__ __align__(16) float g_x[(size_t)BB * LL * DI];           // x part,  [b][l][d]
__device__ __align__(16) float g_z[(size_t)BB * LL * DI];           // z part,  [b][l][d]
__device__ __align__(16) float g_xc[(size_t)2 * BB * LL * DI];      // conv out (unclipped), [dir][b][t][d]
__device__ __align__(16) float g_xdbl[(size_t)2 * BB * LL * XPC];   // x_proj out, [dir][b][t][96]
__device__ __align__(16) float g_delta[(size_t)2 * BB * LL * DI];   // softplus dt, [dir][b][t][d]
__device__ __align__(16) float g_ys[(size_t)2 * BB * LL * DI];      // scan out, [dir][b][t][d]

enum { EPI_INPROJ = 0, EPI_PLAIN = 1, EPI_DT = 2, EPI_OUT = 3 };

__device__ __forceinline__ float silu_f(float z) {
    return z / (1.f + __expf(-z));
}
__device__ __forceinline__ float softplus_dt(float v, float b) {
    float t = v + b;
    t = fminf(fmaxf(t, 1e-5f), 1.0f) + b;
    return (t > 20.f) ? t : __logf(1.f + __expf(t));
}
__device__ __forceinline__ float nan2num(float v) {
    if (isnan(v)) return 0.f;
    if (isinf(v)) return (v > 0.f) ? 1.f : -1.f;
    return v;
}

// ---------------- generic fp32 GEMM: C = A(MxK,row-major,lda) * W(NxK,row-major,ldb)^T ----
// Two-stage smem double buffer + register prefetch: one __syncthreads per K-step.
// EPI_OUT: A synthesized on the fly as (ys_f + rev(ys_b)) * silu(z);
//          A = ys fwd base, W2 = z base, bias2 = ys bwd base (reused slots).
// Other EPIs may batch directions via blockIdx.z (W2/bias2 = dir-1 weights).
template <int BM, int BN, int BK, int TM, int TN, int EPI>
__global__ __launch_bounds__((BM / TM) * (BN / TN))
void gemm_k(const float* __restrict__ A, int lda,
            const float* __restrict__ W, int ldb,
            float* __restrict__ C, int ldc,
            const float* __restrict__ bias,
            float* __restrict__ C2,
            int K,
            const float* __restrict__ W2 = nullptr,
            const float* __restrict__ bias2 = nullptr,
            size_t aStride = 0, size_t cStride = 0)
{
    constexpr int NT   = (BM / TM) * (BN / TN);
    constexpr int NTX  = BN / TN;
    constexpr int KV   = BK / 4;                       // float4s per k-row
    constexpr int A_IT = (BM * KV + NT - 1) / NT;      // float4 loads/thread (A)
    constexpr int B_IT = (BN * KV + NT - 1) / NT;      // float4 loads/thread (B)

    if constexpr (EPI != EPI_OUT) {
        if (blockIdx.z) {                              // dir-batched launch
            A += aStride;
            C += cStride;
            W = W2;
            bias = bias2;
        }
    }

    const float* __restrict__ zBase  = W2;     // EPI_OUT only
    const float* __restrict__ ybBase = bias2;  // EPI_OUT only

    __shared__ float As[2][BK][BM + 4];
    __shared__ float Bs[2][BK][BN + 4];

    const int tid = threadIdx.x;
    const int tx  = tid % NTX;
    const int ty  = tid / NTX;
    const int m0  = blockIdx.y * BM;
    const int n0  = blockIdx.x * BN;

    float4 aReg[A_IT], bReg[B_IT];

    auto ldgA = [&](int k0) {
#pragma unroll
        for (int q = 0; q < A_IT; q++) {
            const int i = tid + q * NT;
            if (A_IT * NT == BM * KV || i < BM * KV) {
                const int r = i / KV, c = i % KV;
                if constexpr (EPI == EPI_OUT) {
                    const int row = m0 + r;
                    const int b   = row / LL, l = row % LL;
                    const size_t off  = (size_t)row * lda + k0 + c * 4;
                    const size_t offb = ((size_t)b * LL + (LL - 1 - l)) * lda + k0 + c * 4;
                    const float4 yf = *reinterpret_cast<const float4*>(A + off);
                    const float4 yb = *reinterpret_cast<const float4*>(ybBase + offb);
                    const float4 zv = *reinterpret_cast<const float4*>(zBase + off);
                    float4 v;
                    v.x = (yf.x + yb.x) * silu_f(zv.x);
                    v.y = (yf.y + yb.y) * silu_f(zv.y);
                    v.z = (yf.z + yb.z) * silu_f(zv.z);
                    v.w = (yf.w + yb.w) * silu_f(zv.w);
                    aReg[q] = v;
                } else {
                    aReg[q] = *reinterpret_cast<const float4*>(
                        A + (size_t)(m0 + r) * lda + k0 + c * 4);
                }
            }
        }
    };
    auto ldgB = [&](int k0) {
#pragma unroll
        for (int q = 0; q < B_IT; q++) {
            const int i = tid + q * NT;
            if (B_IT * NT == BN * KV || i < BN * KV) {
                const int r = i / KV, c = i % KV;
                bReg[q] = *reinterpret_cast<const float4*>(
                    W + (size_t)(n0 + r) * ldb + k0 + c * 4);
            }
        }
    };
    auto stsAB = [&](int s) {
#pragma unroll
        for (int q = 0; q < A_IT; q++) {
            const int i = tid + q * NT;
            if (A_IT * NT == BM * KV || i < BM * KV) {
                const int r = i / KV, c = i % KV;
                As[s][c * 4 + 0][r] = aReg[q].x;
                As[s][c * 4 + 1][r] = aReg[q].y;
                As[s][c * 4 + 2][r] = aReg[q].z;
                As[s][c * 4 + 3][r] = aReg[q].w;
            }
        }
#pragma unroll
        for (int q = 0; q < B_IT; q++) {
            const int i = tid + q * NT;
            if (B_IT * NT == BN * KV || i < BN * KV) {
                const int r = i / KV, c = i % KV;
                Bs[s][c * 4 + 0][r] = bReg[q].x;
                Bs[s][c * 4 + 1][r] = bReg[q].y;
                Bs[s][c * 4 + 2][r] = bReg[q].z;
                Bs[s][c * 4 + 3][r] = bReg[q].w;
            }
        }
    };

    float acc[TM][TN];
#pragma unroll
    for (int i = 0; i < TM; i++)
#pragma unroll
        for (int j = 0; j < TN; j++) acc[i][j] = 0.f;

    ldgA(0);
    ldgB(0);
    stsAB(0);
    __syncthreads();

    int s = 0;
    for (int k0 = 0; k0 < K; k0 += BK) {
        const bool more = (k0 + BK < K);
        if (more) {            // prefetch next tile into registers
            ldgA(k0 + BK);
            ldgB(k0 + BK);
        }

#pragma unroll
        for (int kk = 0; kk < BK; kk++) {
            float a[TM], b[TN];
#pragma unroll
            for (int q = 0; q < TM / 4; q++)
                *reinterpret_cast<float4*>(&a[q * 4]) =
                    *reinterpret_cast<const float4*>(&As[s][kk][ty * TM + q * 4]);
            if constexpr (TN % 4 == 0) {
#pragma unroll
                for (int q = 0; q < TN / 4; q++)
                    *reinterpret_cast<float4*>(&b[q * 4]) =
                        *reinterpret_cast<const float4*>(&Bs[s][kk][tx * TN + q * 4]);
            } else {
                *reinterpret_cast<float2*>(b) =
                    *reinterpret_cast<const float2*>(&Bs[s][kk][tx * TN]);
            }
#pragma unroll
            for (int i = 0; i < TM; i++)
#pragma unroll
                for (int j = 0; j < TN; j++) acc[i][j] += a[i] * b[j];
        }

        if (more) {            // publish next stage; single barrier per step
            stsAB(s ^ 1);
            __syncthreads();
        }
        s ^= 1;
    }

    // ---------------- epilogue: float4 stores (dense sectors, no 8x amplification) -----
    if constexpr (TN % 4 == 0) {
#pragma unroll
        for (int i = 0; i < TM; i++) {
            const int r = m0 + ty * TM + i;
#pragma unroll
            for (int jq = 0; jq < TN / 4; jq++) {
                const int c = n0 + tx * TN + jq * 4;
                float4 v = *reinterpret_cast<const float4*>(&acc[i][jq * 4]);
                if constexpr (EPI == EPI_INPROJ) {
                    // whole BN tile lies entirely in x or in z (DI % BN == 0)
                    float* dst = (n0 < DI) ? (C  + (size_t)r * DI + c)
                                           : (C2 + (size_t)r * DI + (c - DI));
                    *reinterpret_cast<float4*>(dst) = v;
                } else if constexpr (EPI == EPI_DT) {
                    const float4 bv = *reinterpret_cast<const float4*>(bias + c);
                    v.x = softplus_dt(v.x, bv.x);
                    v.y = softplus_dt(v.y, bv.y);
                    v.z = softplus_dt(v.z, bv.z);
                    v.w = softplus_dt(v.w, bv.w);
                    *reinterpret_cast<float4*>(C + (size_t)r * ldc + c) = v;
                } else if constexpr (EPI == EPI_OUT) {
                    v.x = nan2num(v.x);
                    v.y = nan2num(v.y);
                    v.z = nan2num(v.z);
                    v.w = nan2num(v.w);
                    *reinterpret_cast<float4*>(C + (size_t)r * ldc + c) = v;
                } else {
                    *reinterpret_cast<float4*>(C + (size_t)r * ldc + c) = v;
                }
            }
        }
    } else {   // scalar fallback (x_proj 64x32 tile, TN=2)
#pragma unroll
        for (int i = 0; i < TM; i++) {
            const int r = m0 + ty * TM + i;
#pragma unroll
            for (int j = 0; j < TN; j++) {
                const int c = n0 + tx * TN + j;
                C[(size_t)r * ldc + c] = acc[i][j];
            }
        }
    }
}

// ---------------- depthwise causal conv, gather-based, 4 channels per thread -------------
// out[dir][b][t][d4] = bias[d4] + sum_j w[d4][j] * xrev[t-3+j][d4]  (all float4)
__global__ void conv_k(const float* __restrict__ wf, const float* __restrict__ bf,
                       const float* __restrict__ wb, const float* __restrict__ bb)
{
    const int idx = blockIdx.x * blockDim.x + threadIdx.x;   // over 2*BB*LL*(DI/4)
    if (idx >= 2 * BB * LL * (DI / 4)) return;
    const int d4  = (idx % (DI / 4)) * 4;
    const int t   = (idx / (DI / 4)) % LL;
    const int b   = (idx / ((DI / 4) * LL)) % BB;
    const int dir = idx / ((DI / 4) * LL * BB);

    const float* wsrc = (dir ? wb : wf) + d4 * 4;            // 4 channels x 4 taps, contiguous
    const float4 w0 = *reinterpret_cast<const float4*>(wsrc + 0);   // taps of channel d4+0
    const float4 w1 = *reinterpret_cast<const float4*>(wsrc + 4);
    const float4 w2 = *reinterpret_cast<const float4*>(wsrc + 8);
    const float4 w3 = *reinterpret_cast<const float4*>(wsrc + 12);

    float4 acc = *reinterpret_cast<const float4*>((dir ? bb : bf) + d4);

    const float* xb = g_x + (size_t)b * LL * DI + d4;
#pragma unroll
    for (int j = 0; j < 4; j++) {
        const int tt = t - 3 + j;                 // position in (possibly reversed) seq
        if (tt >= 0) {
            const int src_l = dir ? (LL - 1 - tt) : tt;
            const float4 xv = *reinterpret_cast<const float4*>(xb + (size_t)src_l * DI);
            const float t0 = j == 0 ? w0.x : j == 1 ? w0.y : j == 2 ? w0.z : w0.w;
            const float t1 = j == 0 ? w1.x : j == 1 ? w1.y : j == 2 ? w1.z : w1.w;
            const float t2 = j == 0 ? w2.x : j == 1 ? w2.y : j == 2 ? w2.z : w2.w;
            const float t3 = j == 0 ? w3.x : j == 1 ? w3.y : j == 2 ? w3.z : w3.w;
            acc.x += t0 * xv.x;
            acc.y += t1 * xv.y;
            acc.z += t2 * xv.z;
            acc.w += t3 * xv.w;
        }
    }
    float* outp = g_xc + ((size_t)((dir * BB + b) * LL + t)) * DI + d4;
    *reinterpret_cast<float4*>(outp) = acc;
}

// ---------------- selective scan (one thread per (dir,b,d), 16 states in regs) --------------
// Register-pipelined: t+1 inputs load while t computes.
__global__ void scan_k(const float* __restrict__ Alog_f, const float* __restrict__ Df,
                       const float* __restrict__ Alog_b, const float* __restrict__ Db)
{
    const int gid = blockIdx.x * blockDim.x + threadIdx.x;
    if (gid >= 2 * BB * DI) return;
    const int dir = gid / (BB * DI);
    const int rem = gid % (BB * DI);
    const int b = rem / DI, d = rem % DI;

    const float* Alog = dir ? Alog_b : Alog_f;
    const float  Dv   = dir ? Db[d] : Df[d];

    float Av[DS];
    bool fast = true;
#pragma unroll
    for (int n = 0; n < DS; n++) {
        Av[n] = -expf(Alog[d * DS + n]);
        fast = fast && (fabsf(Av[n] + (float)(n + 1)) < 1e-3f);
    }

    float h[DS];
#pragma unroll
    for (int n = 0; n < DS; n++) h[n] = 0.f;

    const size_t rowbase = (size_t)(dir * BB + b) * LL;
    const float* up = g_xc    + rowbase * DI  + d;
    const float* dp = g_delta + rowbase * DI  + d;
    const float* bc = g_xdbl  + rowbase * XPC + RNK;   // B then C, 32 floats
    float*       yp = g_ys    + rowbase * DI  + d;

    // prefetch t=0
    float  u_c   = up[0];
    float  dlt_c = dp[0];
    float4 q_c[8];
#pragma unroll
    for (int k = 0; k < 8; k++)
        q_c[k] = reinterpret_cast<const float4*>(bc)[k];

    for (int t = 0; t < LL; t++) {
        // issue t+1 loads first (independent of current compute)
        float  u_n = 0.f, dlt_n = 0.f;
        float4 q_n[8];
        if (t + 1 < LL) {
            u_n   = up[(size_t)(t + 1) * DI];
            dlt_n = dp[(size_t)(t + 1) * DI];
            const float4* qq = reinterpret_cast<const float4*>(bc + (size_t)(t + 1) * XPC);
#pragma unroll
            for (int k = 0; k < 8; k++) q_n[k] = qq[k];
        }

        const float u   = fminf(fmaxf(u_c, -10.f), 10.f);
        const float dlt = dlt_c;

        float Bv[DS], Cv[DS];
#pragma unroll
        for (int k = 0; k < 4; k++) *reinterpret_cast<float4*>(&Bv[k * 4]) = q_c[k];
#pragma unroll
        for (int k = 0; k < 4; k++) *reinterpret_cast<float4*>(&Cv[k * 4]) = q_c[4 + k];

        const float du = dlt * u;
        float y = u * Dv;
        if (fast) {
            // A[n] == -(n+1): need E^(n+1), E = exp(-dlt). Log-depth power tree.
            const float E1  = __expf(-dlt);
            const float E2  = E1 * E1;
            const float E3  = E2 * E1;
            const float E4  = E2 * E2;
            const float E8  = E4 * E4;
            const float E12 = E8 * E4;
            float pw[DS];
            pw[0]  = E1;        pw[1]  = E2;        pw[2]  = E3;        pw[3]  = E4;
            pw[4]  = E4 * E1;   pw[5]  = E4 * E2;   pw[6]  = E4 * E3;   pw[7]  = E8;
            pw[8]  = E8 * E1;   pw[9]  = E8 * E2;   pw[10] = E8 * E3;   pw[11] = E12;
            pw[12] = E12 * E1;  pw[13] = E12 * E2;  pw[14] = E12 * E3;  pw[15] = E8 * E8;
#pragma unroll
            for (int n = 0; n < DS; n++) {
                h[n] = pw[n] * h[n] + du * Bv[n];
                y += h[n] * Cv[n];
            }
        } else {
#pragma unroll
            for (int n = 0; n < DS; n++) {
                const float dA = __expf(dlt * Av[n]);
                h[n] = dA * h[n] + du * Bv[n];
                y += h[n] * Cv[n];
            }
        }
        yp[(size_t)t * DI] = y;

        // rotate buffers
        u_c = u_n; dlt_c = dlt_n;
#pragma unroll
        for (int k = 0; k < 8; k++) q_c[k] = q_n[k];
    }
}

// ---------------- host ----------------
extern "C" void kernel_launch(void* const* d_in, const int* in_sizes, int n_in,
                              void* d_out, int out_size)
{
    (void)in_sizes; (void)n_in; (void)out_size;

    const float* hidden  = (const float*)d_in[0];
    const float* inw     = (const float*)d_in[1];
    const float* convw_f = (const float*)d_in[2];
    const float* convb_f = (const float*)d_in[3];
    const float* xpw_f   = (const float*)d_in[4];
    const float* dtw_f   = (const float*)d_in[5];
    const float* dtb_f   = (const float*)d_in[6];
    const float* Alog_f  = (const float*)d_in[7];
    const float* Dv_f    = (const float*)d_in[8];
    const float* convw_b = (const float*)d_in[9];
    const float* convb_b = (const float*)d_in[10];
    const float* xpw_b   = (const float*)d_in[11];
    const float* dtw_b   = (const float*)d_in[12];
    const float* dtb_b   = (const float*)d_in[13];
    const float* Alog_b  = (const float*)d_in[14];
    const float* Dv_b    = (const float*)d_in[15];
    const float* outw    = (const float*)d_in[16];

    float *p_x, *p_z, *p_xc, *p_xdbl, *p_delta, *p_ys;
    cudaGetSymbolAddress((void**)&p_x,     g_x);
    cudaGetSymbolAddress((void**)&p_z,     g_z);
    cudaGetSymbolAddress((void**)&p_xc,    g_xc);
    cudaGetSymbolAddress((void**)&p_xdbl,  g_xdbl);
    cudaGetSymbolAddress((void**)&p_delta, g_delta);
    cudaGetSymbolAddress((void**)&p_ys,    g_ys);

    const int MROWS = BB * LL;  // 2048

    // 1) in_proj: (2048x1024) @ (4096x1024)^T -> split into x and z (both [b][l][d])
    gemm_k<128, 128, 16, 8, 8, EPI_INPROJ>
        <<<dim3((2 * DI) / 128, MROWS / 128), 256>>>(hidden, DM, inw, DM,
                                                     p_x, 0, nullptr, p_z, DM);

    // 2) depthwise causal conv, both directions (gather form, float4)
    conv_k<<<(2 * BB * LL * (DI / 4)) / 256, 256>>>(convw_f, convb_f, convw_b, convb_b);

    // 3) x_proj, both directions in ONE launch (blockIdx.z = dir): 192 CTAs
    gemm_k<64, 32, 16, 4, 2, EPI_PLAIN>
        <<<dim3(XPC / 32, MROWS / 64, 2), 256>>>(
            p_xc, DI, xpw_f, DI, p_xdbl, XPC, nullptr, nullptr, DI,
            xpw_b, nullptr, (size_t)MROWS * DI, (size_t)MROWS * XPC);

    // 4) dt_proj (+clip+softplus), both directions in ONE launch: 512 CTAs
    gemm_k<128, 128, 16, 8, 8, EPI_DT>
        <<<dim3(DI / 128, MROWS / 128, 2), 256>>>(
            p_xdbl, XPC, dtw_f, RNK, p_delta, DI, dtb_f, nullptr, RNK,
            dtw_b, dtb_b, (size_t)MROWS * XPC, (size_t)MROWS * DI);

    // 5) selective scan, both directions (register-pipelined)
    scan_k<<<(2 * BB * DI) / 128, 128>>>(Alog_f, Dv_f, Alog_b, Dv_b);

    // 6) out_proj with fused combine+silu in the A-loader -> d_out (with nan_to_num)
    //    128x64 tile: 256 CTAs (vs 128) -> no idle SMs, 2-3 CTAs/SM resident.
    gemm_k<128, 64, 16, 8, 4, EPI_OUT>
        <<<dim3(DM / 64, MROWS / 128), 256>>>(
            p_ys, DI, outw, DI, (float*)d_out, DM, nullptr, nullptr, DI,
            p_z, p_ys + (size_t)BB * LL * DI, 0, 0);
}